// round 4
// baseline (speedup 1.0000x reference)
#include <cuda_runtime.h>

// MLP_Interpolate: 4x nearest upsample + 2-layer MLP.
// Split-C/split-J scheme: 2 threads per input pixel (lane pair 2t, 2t+1).
//   half h handles input channels c in [32h, 32h+32) for the base GEMM,
//   exchanges 32-dim base partials with its partner via shfl.bfly(1),
//   then runs the epilogue for output rows j in {2h, 2h+1} only.
// All heavy math packed f32x2. W1 rows >=32 stored quad-rotated so the
// lane pair's concurrent LDS.128 hit different banks.

namespace {

typedef unsigned long long ull;

__device__ __forceinline__ ull pk(float lo, float hi) {
    ull r; asm("mov.b64 %0, {%1, %2};" : "=l"(r) : "f"(lo), "f"(hi)); return r;
}
__device__ __forceinline__ float2 upk(ull a) {
    float2 r; asm("mov.b64 {%0, %1}, %2;" : "=f"(r.x), "=f"(r.y) : "l"(a)); return r;
}
__device__ __forceinline__ ull addx2(ull a, ull b) {
    ull d; asm("add.rn.f32x2 %0, %1, %2;" : "=l"(d) : "l"(a), "l"(b)); return d;
}
__device__ __forceinline__ ull fmax2p(ull a, ull b, ull c) {
    ull d; asm("fma.rn.f32x2 %0, %1, %2, %3;" : "=l"(d) : "l"(a), "l"(b), "l"(c)); return d;
}
__device__ __forceinline__ ull relu2(ull s) {
    float2 v = upk(s);
    return pk(fmaxf(v.x, 0.f), fmaxf(v.y, 0.f));
}

constexpr int Hh = 128;
constexpr int Wd = 128;
constexpr int HW = Hh * Wd;
constexpr int OUT = 512;

__global__ __launch_bounds__(128, 5) void mlp_interp_kernel(
    const float* __restrict__ x,   // [B,64,128,128]
    const float* __restrict__ W1,  // [66,64]
    const float* __restrict__ b1,  // [64]
    const float* __restrict__ W2,  // [64,3]
    const float* __restrict__ b2,  // [3]
    float* __restrict__ out)       // [B,3,512,512]
{
    // w1s[c][dims], rows c>=32 have each 128B dim-block rotated by one 16B quad
    __shared__ float      w1s[64 * 64];
    __shared__ ulonglong2 Cp[4][65];     // Cp[j][i] = packed (k01, k23); stride 65 -> bank stagger
    __shared__ ulonglong2 W2p[64];       // {.x=(W2[i][0] dup), .y=(W2[i][1] dup)}
    __shared__ ull        W2q[64];       // (W2[i][2] dup)
    __shared__ float      b2s[4];

    const int tid  = threadIdx.x;
    const int half = tid & 1;            // which c-half / j-half this lane owns
    const int p    = tid >> 1;           // pixel within half-row, 0..63
    const int cta  = blockIdx.x;         // 1024 CTAs: (b, h, half-row)
    const int hr   = cta & 1;
    const int h    = (cta >> 1) & (Hh - 1);
    const int b    = cta >> 8;
    const int wloc = hr * 64 + p;        // input col

    // ---- staging ----
    if (tid < 64) {
        // W1 rows with quad rotation for rows >= 32
        const int c = tid;
        const int rrow = c >> 5;
        #pragma unroll
        for (int k = 0; k < 64; k++) {
            const int d = (k + ((c & 7) << 3)) & 63;       // stagger to avoid STS conflicts
            const int pos = c * 64 + (d & 32) +
                            (((((d >> 2) & 7) + rrow) & 7) << 2) + (d & 3);
            w1s[pos] = W1[c * 64 + d];
        }
    } else {
        const int c = tid - 64;
        const float w64 = W1[64 * 64 + c];
        const float w65 = W1[64 * 64 + 64 + c];
        const float bb  = b1[c];
        #pragma unroll
        for (int j = 0; j < 4; j++) {
            const float rj = -0.75f + 0.5f * (float)j;
            const float base = fmaf(rj, w64, bb);
            float cv[4];
            #pragma unroll
            for (int k = 0; k < 4; k++)
                cv[k] = fmaf(-0.75f + 0.5f * (float)k, w65, base);
            Cp[j][c].x = pk(cv[0], cv[1]);
            Cp[j][c].y = pk(cv[2], cv[3]);
        }
        const float w20 = W2[c * 3 + 0];
        const float w21 = W2[c * 3 + 1];
        const float w22 = W2[c * 3 + 2];
        W2p[c].x = pk(w20, w20);
        W2p[c].y = pk(w21, w21);
        W2q[c]   = pk(w22, w22);
        if (c < 3) b2s[c] = b2[c];
    }
    __syncthreads();

    // x pointer for this lane's c-half
    const float* xp = x + ((size_t)b * 64 + half * 32) * HW + h * Wd + wloc;

    // accumulators: acc[ch][jj][kp], jj over this lane's 2 output rows
    ull acc[3][2][2];
    #pragma unroll
    for (int ch = 0; ch < 3; ch++) {
        const ull bv = pk(b2s[ch], b2s[ch]);
        acc[ch][0][0] = bv; acc[ch][0][1] = bv;
        acc[ch][1][0] = bv; acc[ch][1][1] = bv;
    }

    const ulonglong2* cp0 = &Cp[half * 2][0];
    const ulonglong2* cp1 = &Cp[half * 2 + 1][0];

    #pragma unroll 1
    for (int chunk = 0; chunk < 2; chunk++) {
        // ---- base partial over my 32 channels, dims [32*chunk, 32*chunk+32) ----
        ull bcp[16];
        #pragma unroll
        for (int m = 0; m < 16; m++) bcp[m] = 0ull;

        // 8 quad pointers with per-half rotation (conflict-free lane pairs)
        const char* wbase = (const char*)w1s + half * 8192 + chunk * 128;

        #pragma unroll 8
        for (int cl = 0; cl < 32; cl++) {
            const float fc = xp[(size_t)cl * HW];
            const ull fcd = pk(fc, fc);
            #pragma unroll
            for (int q = 0; q < 8; q++) {
                const ulonglong2 wv = *(const ulonglong2*)(
                    wbase + (size_t)cl * 256 + (((q + half) & 7) << 4));
                bcp[2 * q]     = fmax2p(fcd, wv.x, bcp[2 * q]);
                bcp[2 * q + 1] = fmax2p(fcd, wv.y, bcp[2 * q + 1]);
            }
        }

        // ---- exchange partials with partner lane: full base in both lanes ----
        #pragma unroll
        for (int m = 0; m < 16; m++)
            bcp[m] = addx2(bcp[m], __shfl_xor_sync(0xffffffffu, bcp[m], 1));

        // ---- epilogue: fold 32 dims into my 2 output rows ----
        #pragma unroll 4
        for (int m = 0; m < 16; m++) {
            const float2 bcv = upk(bcp[m]);
            #pragma unroll
            for (int sub = 0; sub < 2; sub++) {
                const int i = chunk * 32 + 2 * m + sub;
                const float bs = sub ? bcv.y : bcv.x;
                const ull bd = pk(bs, bs);
                const ulonglong2 wd01 = W2p[i];   // warp-uniform
                const ull        wdq  = W2q[i];
                #pragma unroll
                for (int jj = 0; jj < 2; jj++) {
                    const ulonglong2 cc = (jj ? cp1 : cp0)[i];
                    const ull h01 = relu2(addx2(bd, cc.x));
                    const ull h23 = relu2(addx2(bd, cc.y));
                    acc[0][jj][0] = fmax2p(h01, wd01.x, acc[0][jj][0]);
                    acc[0][jj][1] = fmax2p(h23, wd01.x, acc[0][jj][1]);
                    acc[1][jj][0] = fmax2p(h01, wd01.y, acc[1][jj][0]);
                    acc[1][jj][1] = fmax2p(h23, wd01.y, acc[1][jj][1]);
                    acc[2][jj][0] = fmax2p(h01, wdq,    acc[2][jj][0]);
                    acc[2][jj][1] = fmax2p(h23, wdq,    acc[2][jj][1]);
                }
            }
        }
    }

    // ---- stores: this lane owns rows j = 2*half + {0,1} ----
    float4* op = (float4*)out;
    #pragma unroll
    for (int ch = 0; ch < 3; ch++) {
        #pragma unroll
        for (int jj = 0; jj < 2; jj++) {
            const int j = half * 2 + jj;
            const float2 a0 = upk(acc[ch][jj][0]);
            const float2 a1 = upk(acc[ch][jj][1]);
            const size_t idx =
                ((size_t)(b * 3 + ch) * OUT + (4 * h + j)) * (OUT / 4) + wloc;
            op[idx] = make_float4(a0.x, a0.y, a1.x, a1.y);
        }
    }
}

}  // namespace

extern "C" void kernel_launch(void* const* d_in, const int* in_sizes, int n_in,
                              void* d_out, int out_size) {
    const float* x  = (const float*)d_in[0];
    const float* W1 = (const float*)d_in[1];
    const float* b1 = (const float*)d_in[2];
    const float* W2 = (const float*)d_in[3];
    const float* b2 = (const float*)d_in[4];
    float* out = (float*)d_out;

    // 1024 CTAs (half input row each), 128 threads (2 threads per pixel)
    mlp_interp_kernel<<<1024, 128>>>(x, W1, b1, W2, b2, out);
}

// round 5
// speedup vs baseline: 1.2469x; 1.2469x over previous
#include <cuda_runtime.h>

// MLP_Interpolate: 4x nearest upsample + 2-layer MLP, f32x2 packed.
// i-split + j-split: 2 threads per pixel (lane pair 2t, 2t+1).
//   lane half s computes base[i] for i in [32s, 32s+32) over ALL 64 channels
//   (lane pairs read identical x addresses -> no extra LDG sectors),
//   exchanges packed 16-dim base sub-chunks via shfl.bfly(1),
//   then folds all 64 hidden dims into only its 2 output rows j in {2s,2s+1}.
// Bank-conflict-free by layout: w1s quads interleaved by s (pair addrs 16B
// apart), W2 tables interleaved by i-half, Cp rows padded to stride 65.

namespace {

typedef unsigned long long ull;

__device__ __forceinline__ ull pk(float lo, float hi) {
    ull r; asm("mov.b64 %0, {%1, %2};" : "=l"(r) : "f"(lo), "f"(hi)); return r;
}
__device__ __forceinline__ float2 upk(ull a) {
    float2 r; asm("mov.b64 {%0, %1}, %2;" : "=f"(r.x), "=f"(r.y) : "l"(a)); return r;
}
__device__ __forceinline__ ull addx2(ull a, ull b) {
    ull d; asm("add.rn.f32x2 %0, %1, %2;" : "=l"(d) : "l"(a), "l"(b)); return d;
}
__device__ __forceinline__ ull fmax2p(ull a, ull b, ull c) {
    ull d; asm("fma.rn.f32x2 %0, %1, %2, %3;" : "=l"(d) : "l"(a), "l"(b), "l"(c)); return d;
}
__device__ __forceinline__ ull relu2(ull v) {
    float2 t = upk(v);
    return pk(fmaxf(t.x, 0.f), fmaxf(t.y, 0.f));
}

constexpr int Hh = 128;
constexpr int Wd = 128;
constexpr int HW = Hh * Wd;
constexpr int OUT = 512;

// interleaved w1s position (floats): dims d of row c at
//   c*64 + ((d&31)>>2)*8 + (d>>5)*4 + (d&3)
// so the lane pair's concurrent LDS.128 addresses differ by 16B.
__device__ __forceinline__ int w1pos(int c, int d) {
    return c * 64 + (((d & 31) >> 2) << 3) + ((d >> 5) << 2) + (d & 3);
}
// interleaved W2 index: i and i+32 adjacent
__device__ __forceinline__ int pos2(int i) { return ((i & 31) << 1) + (i >> 5); }

__global__ __launch_bounds__(128, 6) void mlp_interp_kernel(
    const float* __restrict__ x,   // [B,64,128,128]
    const float* __restrict__ W1,  // [66,64]
    const float* __restrict__ b1,  // [64]
    const float* __restrict__ W2,  // [64,3]
    const float* __restrict__ b2,  // [3]
    float* __restrict__ out)       // [B,3,512,512]
{
    __shared__ float      w1s[64 * 64];   // interleaved (see w1pos)
    __shared__ ulonglong2 Cp[4][65];      // Cp[j][i] = packed (k01, k23); stride 65
    __shared__ ulonglong2 W2p[64];        // at pos2(i): {.x=dup W2[i][0], .y=dup W2[i][1]}
    __shared__ ull        W2q[64];        // at pos2(i): dup W2[i][2]
    __shared__ float      b2s[4];

    const int tid  = threadIdx.x;
    const int s    = tid & 1;             // hidden-dim half / output-row half
    const int p    = tid >> 1;            // pixel within half-row, 0..63
    const int cta  = blockIdx.x;          // 1024: (b, h, half-row)
    const int hr   = cta & 1;
    const int h    = (cta >> 1) & (Hh - 1);
    const int b    = cta >> 8;
    const int wloc = hr * 64 + p;

    // ---- staging ----
    #pragma unroll
    for (int r = 0; r < 32; r++) {
        const int flat = r * 128 + tid;
        w1s[w1pos(flat >> 6, flat & 63)] = W1[flat];
    }
    if (tid >= 64) {
        const int c = tid - 64;
        const float w64 = W1[64 * 64 + c];
        const float w65 = W1[64 * 64 + 64 + c];
        const float bb  = b1[c];
        #pragma unroll
        for (int j = 0; j < 4; j++) {
            const float rj = -0.75f + 0.5f * (float)j;
            const float base = fmaf(rj, w64, bb);
            float cv[4];
            #pragma unroll
            for (int k = 0; k < 4; k++)
                cv[k] = fmaf(-0.75f + 0.5f * (float)k, w65, base);
            Cp[j][c].x = pk(cv[0], cv[1]);
            Cp[j][c].y = pk(cv[2], cv[3]);
        }
        const float w20 = W2[c * 3 + 0];
        const float w21 = W2[c * 3 + 1];
        const float w22 = W2[c * 3 + 2];
        W2p[pos2(c)].x = pk(w20, w20);
        W2p[pos2(c)].y = pk(w21, w21);
        W2q[pos2(c)]   = pk(w22, w22);
        if (c < 3) b2s[c] = b2[c];
    }
    __syncthreads();

    const float* xp = x + (size_t)b * 64 * HW + h * Wd + wloc;  // lane pairs share addr

    // acc[ch][jj][kp]: my 2 output rows (j = 2s+jj), packed col pairs
    ull acc[3][2][2];
    #pragma unroll
    for (int ch = 0; ch < 3; ch++) {
        const ull bv = pk(b2s[ch], b2s[ch]);
        acc[ch][0][0] = bv; acc[ch][0][1] = bv;
        acc[ch][1][0] = bv; acc[ch][1][1] = bv;
    }

    const ulonglong2* cp0 = &Cp[2 * s][0];
    const ulonglong2* cp1 = &Cp[2 * s + 1][0];
    const int iobase_s = 32 * s;            // my dim-range base
    const int ipbase_s = 32 * (1 - s);      // partner's

    #pragma unroll 1
    for (int t = 0; t < 2; t++) {
        // ---- base for my dims [32s+16t, 32s+16t+16) over all 64 channels ----
        ull bcp[8];
        #pragma unroll
        for (int m = 0; m < 8; m++) bcp[m] = 0ull;

        const float* wq = w1s + t * 32 + s * 4;   // + c*64 + qq*8

        #pragma unroll 8
        for (int c = 0; c < 64; c++) {
            const float fc = xp[(size_t)c * HW];
            const ull fcd = pk(fc, fc);
            const float* wr = wq + c * 64;
            #pragma unroll
            for (int qq = 0; qq < 4; qq++) {
                const ulonglong2 wv = *(const ulonglong2*)(wr + qq * 8);
                bcp[2 * qq]     = fmax2p(fcd, wv.x, bcp[2 * qq]);
                bcp[2 * qq + 1] = fmax2p(fcd, wv.y, bcp[2 * qq + 1]);
            }
        }

        // ---- exchange: partner's complete base for its 16 dims ----
        ull bcpO[8];
        #pragma unroll
        for (int m = 0; m < 8; m++)
            bcpO[m] = __shfl_xor_sync(0xffffffffu, bcp[m], 1);

        // ---- epilogue: fold 32 dims (mine + partner's) into my 2 rows ----
        const int io = iobase_s + 16 * t;   // global i base of bcp
        const int ip = ipbase_s + 16 * t;   // global i base of bcpO

        #pragma unroll 4
        for (int m = 0; m < 8; m++) {
            #pragma unroll
            for (int src = 0; src < 2; src++) {
                const float2 bv = upk(src ? bcpO[m] : bcp[m]);
                const int ib = (src ? ip : io) + 2 * m;
                #pragma unroll
                for (int sub = 0; sub < 2; sub++) {
                    const int i = ib + sub;
                    const float bs = sub ? bv.y : bv.x;
                    const ull bd = pk(bs, bs);
                    const ulonglong2 wd01 = W2p[pos2(i)];
                    const ull        wdq  = W2q[pos2(i)];
                    #pragma unroll
                    for (int jj = 0; jj < 2; jj++) {
                        const ulonglong2 cc = (jj ? cp1 : cp0)[i];
                        const ull h01 = relu2(addx2(bd, cc.x));
                        const ull h23 = relu2(addx2(bd, cc.y));
                        acc[0][jj][0] = fmax2p(h01, wd01.x, acc[0][jj][0]);
                        acc[0][jj][1] = fmax2p(h23, wd01.x, acc[0][jj][1]);
                        acc[1][jj][0] = fmax2p(h01, wd01.y, acc[1][jj][0]);
                        acc[1][jj][1] = fmax2p(h23, wd01.y, acc[1][jj][1]);
                        acc[2][jj][0] = fmax2p(h01, wdq,    acc[2][jj][0]);
                        acc[2][jj][1] = fmax2p(h23, wdq,    acc[2][jj][1]);
                    }
                }
            }
        }
    }

    // ---- stores: this lane owns rows j = 2s + {0,1} ----
    float4* op = (float4*)out;
    #pragma unroll
    for (int ch = 0; ch < 3; ch++) {
        #pragma unroll
        for (int jj = 0; jj < 2; jj++) {
            const int j = 2 * s + jj;
            const float2 a0 = upk(acc[ch][jj][0]);
            const float2 a1 = upk(acc[ch][jj][1]);
            const size_t idx =
                ((size_t)(b * 3 + ch) * OUT + (4 * h + j)) * (OUT / 4) + wloc;
            op[idx] = make_float4(a0.x, a0.y, a1.x, a1.y);
        }
    }
}

}  // namespace

extern "C" void kernel_launch(void* const* d_in, const int* in_sizes, int n_in,
                              void* d_out, int out_size) {
    const float* x  = (const float*)d_in[0];
    const float* W1 = (const float*)d_in[1];
    const float* b1 = (const float*)d_in[2];
    const float* W2 = (const float*)d_in[3];
    const float* b2 = (const float*)d_in[4];
    float* out = (float*)d_out;

    // 1024 CTAs (half input row), 128 threads (2 per pixel: i-split/j-split)
    mlp_interp_kernel<<<1024, 128>>>(x, W1, b1, W2, b2, out);
}

// round 7
// speedup vs baseline: 1.7713x; 1.4206x over previous
#include <cuda_runtime.h>
#include <cuda_bf16.h>
#include <cstdint>
#include <cstring>

// MLP_Interpolate: 4x nearest upsample + 2-layer MLP.
// Base GEMM (X[128px,64c] @ W1[0:64]^T) on the tensor pipe via baseline-PTX
// mma.sync m16n8k16 bf16 (3-term split: Ah*Bh + Al*Bh + Ah*Bl, fp32 accum;
// residual ~1.5e-5 rel). tcgen05 is NOT available (harness emits compute_103
// PTX without the 'a' feature set). Epilogue = round-3 f32x2-packed code.

namespace {

typedef unsigned long long ull;

__device__ __forceinline__ ull pk(float lo, float hi) {
    ull r; asm("mov.b64 %0, {%1, %2};" : "=l"(r) : "f"(lo), "f"(hi)); return r;
}
__device__ __forceinline__ float2 upk(ull a) {
    float2 r; asm("mov.b64 {%0, %1}, %2;" : "=f"(r.x), "=f"(r.y) : "l"(a)); return r;
}
__device__ __forceinline__ ull addx2(ull a, ull b) {
    ull d; asm("add.rn.f32x2 %0, %1, %2;" : "=l"(d) : "l"(a), "l"(b)); return d;
}
__device__ __forceinline__ ull fmax2p(ull a, ull b, ull c) {
    ull d; asm("fma.rn.f32x2 %0, %1, %2, %3;" : "=l"(d) : "l"(a), "l"(b), "l"(c)); return d;
}
__device__ __forceinline__ ull relu2(ull v) {
    float2 t = upk(v);
    return pk(fmaxf(t.x, 0.f), fmaxf(t.y, 0.f));
}
__device__ __forceinline__ uint32_t s2u(const void* p) {
    uint32_t a;
    asm("{ .reg .u64 t; cvta.to.shared.u64 t, %1; cvt.u32.u64 %0, t; }" : "=r"(a) : "l"(p));
    return a;
}
__device__ __forceinline__ uint32_t b2u(float a, float b) {   // bf16x2, low = a
    __nv_bfloat162 t = __floats2bfloat162_rn(a, b);
    uint32_t r; memcpy(&r, &t, 4); return r;
}

__device__ __forceinline__ void ldsm4(uint32_t addr, uint32_t& r0, uint32_t& r1,
                                      uint32_t& r2, uint32_t& r3) {
    asm volatile("ldmatrix.sync.aligned.m8n8.x4.shared.b16 {%0,%1,%2,%3}, [%4];"
                 : "=r"(r0), "=r"(r1), "=r"(r2), "=r"(r3) : "r"(addr));
}
__device__ __forceinline__ void mma16816(float* d, const uint32_t* a,
                                         uint32_t b0, uint32_t b1) {
    asm volatile(
        "mma.sync.aligned.m16n8k16.row.col.f32.bf16.bf16.f32 "
        "{%0,%1,%2,%3}, {%4,%5,%6,%7}, {%8,%9}, {%0,%1,%2,%3};"
        : "+f"(d[0]), "+f"(d[1]), "+f"(d[2]), "+f"(d[3])
        : "r"(a[0]), "r"(a[1]), "r"(a[2]), "r"(a[3]), "r"(b0), "r"(b1));
}

constexpr int Hh = 128, Wd = 128, HW = Hh * Wd, OUT = 512;
constexpr int BSTR = 66;   // base_s row stride in floats (even -> float2 stores)

// dynamic smem layout (bytes). A/B bf16 tiles (XOR-swizzled 128B rows).
// base_s (128 x 66 fp32 = 33792 B) overlays the A/B region after the MMA.
constexpr int S_AHI = 0;            // X_hi  [128][64 bf16]  16384
constexpr int S_ALO = 16384;        // X_lo                  16384
constexpr int S_BHI = 32768;        // W1T_hi [64][64 bf16]   8192
constexpr int S_BLO = 40960;        // W1T_lo                 8192
constexpr int S_CP  = 49152;        // Cp[4][65] ulonglong2   4160
constexpr int S_W2P = S_CP + 4160;  // W2p[64] ulonglong2     1024
constexpr int S_W2Q = S_W2P + 1024; // W2q[64] ull             512
constexpr int S_B2  = S_W2Q + 512;  // b2[4]                    16
constexpr int S_TOTAL = S_B2 + 16;  // 54864 -> 4 CTAs/SM

// split 8 floats into bf16-hi quad + bf16-lo quad
__device__ __forceinline__ void pack8(const float* v, uint4& qh, uint4& ql) {
    float hi[8], lo[8];
    #pragma unroll
    for (int c = 0; c < 8; c++) {
        const float hf = __bfloat162float(__float2bfloat16_rn(v[c]));
        hi[c] = hf; lo[c] = v[c] - hf;
    }
    qh = make_uint4(b2u(hi[0],hi[1]), b2u(hi[2],hi[3]), b2u(hi[4],hi[5]), b2u(hi[6],hi[7]));
    ql = make_uint4(b2u(lo[0],lo[1]), b2u(lo[2],lo[3]), b2u(lo[4],lo[5]), b2u(lo[6],lo[7]));
}

__global__ __launch_bounds__(128, 4)
void mlp_interp_mma(const float* __restrict__ x, const float* __restrict__ W1,
                    const float* __restrict__ b1, const float* __restrict__ W2,
                    const float* __restrict__ b2, float* __restrict__ out)
{
    extern __shared__ char smem[];
    const uint32_t sb = s2u(smem);
    const int tid  = threadIdx.x;
    const int lane = tid & 31;
    const int wid  = tid >> 5;
    const int cta  = blockIdx.x;            // 512: (b, h)
    const int h = cta & (Hh - 1);
    const int b = cta >> 7;

    // ---- stage A: thread = pixel row; split x into bf16 hi/lo, swizzled ----
    const float* xp = x + (size_t)b * 64 * HW + h * Wd + tid;
    #pragma unroll
    for (int q = 0; q < 8; q++) {
        float v[8];
        #pragma unroll
        for (int c = 0; c < 8; c++) v[c] = xp[(size_t)(8 * q + c) * HW];
        uint4 qh, ql;
        pack8(v, qh, ql);
        const uint32_t off = (uint32_t)tid * 128 + (uint32_t)((q ^ (tid & 7)) << 4);
        *(uint4*)(smem + S_AHI + off) = qh;
        *(uint4*)(smem + S_ALO + off) = ql;
    }

    if (tid >= 64) {
        // ---- stage B: row n=i holds W1[c][i] over k=c (so D = X @ W1) ----
        const int i = tid - 64;
        #pragma unroll
        for (int q = 0; q < 8; q++) {
            float v[8];
            #pragma unroll
            for (int c = 0; c < 8; c++) v[c] = W1[(8 * q + c) * 64 + i];
            uint4 qh, ql;
            pack8(v, qh, ql);
            const uint32_t off = (uint32_t)i * 128 + (uint32_t)((q ^ (i & 7)) << 4);
            *(uint4*)(smem + S_BHI + off) = qh;
            *(uint4*)(smem + S_BLO + off) = ql;
        }
    } else {
        // ---- epilogue tables ----
        const int c = tid;
        const float w64 = W1[64 * 64 + c];
        const float w65 = W1[64 * 64 + 64 + c];
        const float bb  = b1[c];
        ulonglong2* Cp  = (ulonglong2*)(smem + S_CP);
        ulonglong2* W2p = (ulonglong2*)(smem + S_W2P);
        ull*        W2q = (ull*)(smem + S_W2Q);
        float*      b2s = (float*)(smem + S_B2);
        #pragma unroll
        for (int j = 0; j < 4; j++) {
            const float rj = -0.75f + 0.5f * (float)j;
            const float base = fmaf(rj, w64, bb);
            float cv[4];
            #pragma unroll
            for (int k = 0; k < 4; k++)
                cv[k] = fmaf(-0.75f + 0.5f * (float)k, w65, base);
            Cp[j * 65 + c].x = pk(cv[0], cv[1]);
            Cp[j * 65 + c].y = pk(cv[2], cv[3]);
        }
        const float w20 = W2[c * 3 + 0];
        const float w21 = W2[c * 3 + 1];
        const float w22 = W2[c * 3 + 2];
        W2p[c].x = pk(w20, w20);
        W2p[c].y = pk(w21, w21);
        W2q[c]   = pk(w22, w22);
        if (c < 3) b2s[c] = b2[c];
    }
    __syncthreads();

    // ---- MMA: warp wid owns px rows [32*wid, 32*wid+32) ----
    float dacc[2][8][4];
    #pragma unroll
    for (int mt = 0; mt < 2; mt++)
        #pragma unroll
        for (int nt = 0; nt < 8; nt++)
            #pragma unroll
            for (int r = 0; r < 4; r++) dacc[mt][nt][r] = 0.f;

    const int m0w = 32 * wid;
    const int rl  = lane & 15;        // row-within-16 for ldmatrix
    const int qhh = lane >> 4;        // k-chunk half select
    const int rx  = lane & 7;         // swizzle XOR key

    #pragma unroll
    for (int term = 0; term < 3; term++) {
        const uint32_t SA = sb + (term == 1 ? S_ALO : S_AHI);
        const uint32_t SB = sb + (term == 2 ? S_BLO : S_BHI);
        #pragma unroll
        for (int kt = 0; kt < 4; kt++) {
            const uint32_t kx = (uint32_t)(((2 * kt + qhh) ^ rx) << 4);
            uint32_t a0[4], a1[4];
            ldsm4(SA + (uint32_t)(m0w + rl) * 128 + kx,      a0[0], a0[1], a0[2], a0[3]);
            ldsm4(SA + (uint32_t)(m0w + 16 + rl) * 128 + kx, a1[0], a1[1], a1[2], a1[3]);
            uint32_t bl0[8], bl1[8];
            #pragma unroll
            for (int ntp = 0; ntp < 4; ntp++) {
                uint32_t r0, r1, r2, r3;
                ldsm4(SB + (uint32_t)(16 * ntp + rl) * 128 + kx, r0, r1, r2, r3);
                bl0[2 * ntp] = r0; bl0[2 * ntp + 1] = r1;
                bl1[2 * ntp] = r2; bl1[2 * ntp + 1] = r3;
            }
            #pragma unroll
            for (int nt = 0; nt < 8; nt++) {
                mma16816(dacc[0][nt], a0, bl0[nt], bl1[nt]);
                mma16816(dacc[1][nt], a1, bl0[nt], bl1[nt]);
            }
        }
    }
    __syncthreads();   // all ldmatrix reads done before base_s overwrites A/B

    // ---- D fragments -> base_s[px][i] (stride BSTR) ----
    float* base_s = (float*)smem;
    {
        const int g = lane >> 2, tg = lane & 3;
        #pragma unroll
        for (int mt = 0; mt < 2; mt++) {
            const int m = m0w + 16 * mt + g;
            #pragma unroll
            for (int nt = 0; nt < 8; nt++) {
                const int col = nt * 8 + 2 * tg;
                *(float2*)(base_s + m * BSTR + col) =
                    make_float2(dacc[mt][nt][0], dacc[mt][nt][1]);
                *(float2*)(base_s + (m + 8) * BSTR + col) =
                    make_float2(dacc[mt][nt][2], dacc[mt][nt][3]);
            }
        }
    }
    __syncthreads();

    // ---- epilogue (round-3 structure), base from base_s ----
    const ulonglong2* Cp  = (const ulonglong2*)(smem + S_CP);
    const ulonglong2* W2p = (const ulonglong2*)(smem + S_W2P);
    const ull*        W2q = (const ull*)(smem + S_W2Q);
    const float*      b2s = (const float*)(smem + S_B2);
    const float*      brow = base_s + tid * BSTR;

    ull acc[3][4][2];
    #pragma unroll
    for (int ch = 0; ch < 3; ch++) {
        const ull bv = pk(b2s[ch], b2s[ch]);
        #pragma unroll
        for (int j = 0; j < 4; j++) { acc[ch][j][0] = bv; acc[ch][j][1] = bv; }
    }

    #pragma unroll 1
    for (int chunk = 0; chunk < 4; chunk++) {
        float dr[16];
        #pragma unroll
        for (int m = 0; m < 16; m++) dr[m] = brow[chunk * 16 + m];

        #pragma unroll
        for (int m = 0; m < 16; m++) {
            const int i = chunk * 16 + m;
            const float bs = dr[m];
            const ull bd = pk(bs, bs);
            const ulonglong2 wd01 = W2p[i];
            const ull        wdq  = W2q[i];
            #pragma unroll
            for (int j = 0; j < 4; j++) {
                const ulonglong2 cc = Cp[j * 65 + i];
                const ull h01 = relu2(addx2(bd, cc.x));
                const ull h23 = relu2(addx2(bd, cc.y));
                acc[0][j][0] = fmax2p(h01, wd01.x, acc[0][j][0]);
                acc[0][j][1] = fmax2p(h23, wd01.x, acc[0][j][1]);
                acc[1][j][0] = fmax2p(h01, wd01.y, acc[1][j][0]);
                acc[1][j][1] = fmax2p(h23, wd01.y, acc[1][j][1]);
                acc[2][j][0] = fmax2p(h01, wdq,    acc[2][j][0]);
                acc[2][j][1] = fmax2p(h23, wdq,    acc[2][j][1]);
            }
        }
    }

    // ---- stores: out[b, ch, 4h+j, 4*tid .. 4*tid+3], coalesced float4 ----
    float4* op = (float4*)out;
    #pragma unroll
    for (int ch = 0; ch < 3; ch++) {
        #pragma unroll
        for (int j = 0; j < 4; j++) {
            const float2 a0 = upk(acc[ch][j][0]);
            const float2 a1 = upk(acc[ch][j][1]);
            const size_t idx =
                ((size_t)(b * 3 + ch) * OUT + (4 * h + j)) * (OUT / 4) + tid;
            op[idx] = make_float4(a0.x, a0.y, a1.x, a1.y);
        }
    }
}

}  // namespace

extern "C" void kernel_launch(void* const* d_in, const int* in_sizes, int n_in,
                              void* d_out, int out_size) {
    const float* x  = (const float*)d_in[0];
    const float* W1 = (const float*)d_in[1];
    const float* b1 = (const float*)d_in[2];
    const float* W2 = (const float*)d_in[3];
    const float* b2 = (const float*)d_in[4];
    float* out = (float*)d_out;

    cudaFuncSetAttribute(mlp_interp_mma,
                         cudaFuncAttributeMaxDynamicSharedMemorySize, S_TOTAL);
    mlp_interp_mma<<<512, 128, S_TOTAL>>>(x, W1, b1, W2, b2, out);
}